// round 10
// baseline (speedup 1.0000x reference)
#include <cuda_runtime.h>
#include <cuda_bf16.h>
#include <stdint.h>

#define BB 8
#define AA 26880
#define KK 2048
#define NCH 105          // 26880/256 chunks per batch
#define SCAP 4096        // staged-key capacity (Nv ~ 1344)
#define PCAP 512         // conflict-pair capacity per batch (expected ~10)
#define RB 32            // blocks per batch in K2
#define TILE 64

// ---------------- device scratch ----------------
__device__ int      g_nv[BB];
__device__ float4   g_boxes[BB][KK];
__device__ unsigned g_paircnt[BB];     // 0 at entry, reset by K3 winner
__device__ unsigned g_pairs[BB][PCAP];
__device__ unsigned g_tiledone[BB];    // 0 at entry, reset by K3 winner

// ======== K2': local compaction + rank sort + tail fill (2-kernel pipeline, no K1) ========
// Every block of batch b rebuilds the SAME deterministic key array in shared:
// pass 1 counts per 256-anchor chunk, prefix, pass 2 places keys chunk-ordered.
// key = (score_bits << 32) | (0xFFFFFFFF - idx): descending key order gives
// score desc, idx asc on ties (positive floats are bit-order-preserving).
__global__ void __launch_bounds__(256) k_main(const float* __restrict__ preds,
                                              float* __restrict__ out) {
    const int b = blockIdx.y, bl = blockIdx.x;   // bl in [0, RB)
    const int t = threadIdx.x, wid = t >> 5, lane = t & 31;

    __shared__ unsigned long long sk[SCAP];      // 32 KB
    __shared__ unsigned scv[NCH];
    __shared__ unsigned scpre[NCH + 1];
    __shared__ unsigned swc[8];
    __shared__ unsigned short rp[64][4];
    __shared__ unsigned wsum[8];

    const float* basep = preds + (size_t)b * 5 * AA;
    const float* sc = basep + (size_t)4 * AA;

    // ---- pass 1: per-chunk valid counts ----
    for (int x = t; x < NCH; x += 256) scv[x] = 0u;
    __syncthreads();
    #pragma unroll 4
    for (int it = 0; it < 27; it++) {
        int a0 = it * 1024 + t * 4;
        int v = 0;
        if (a0 < AA) {
            float4 s4 = *(const float4*)(sc + a0);
            v = (int)(s4.x >= 0.1f) + (int)(s4.y >= 0.1f)
              + (int)(s4.z >= 0.1f) + (int)(s4.w >= 0.1f);
        }
        int tot = v;
        #pragma unroll
        for (int off = 16; off; off >>= 1)
            tot += __shfl_xor_sync(0xFFFFFFFFu, tot, off);
        if (lane == 0 && tot) atomicAdd(&scv[4 * it + (wid >> 1)], (unsigned)tot);
    }
    __syncthreads();
    if (t == 0) {
        unsigned run = 0;
        for (int x = 0; x < NCH; x++) { scpre[x] = run; run += scv[x]; }
        scpre[NCH] = run;
    }
    __syncthreads();
    unsigned cnt = scpre[NCH]; if (cnt > SCAP) cnt = SCAP;
    int Nv = ((int)cnt < KK) ? (int)cnt : KK;
    if (bl == 0 && t == 0) g_nv[b] = Nv;

    // ---- pass 2: place keys at deterministic chunk-ordered positions (L1-hot reads) ----
    for (int it = 0; it < 27; it++) {
        int a0 = it * 1024 + t * 4;
        unsigned m = 0;
        float4 s4 = make_float4(0.f, 0.f, 0.f, 0.f);
        if (a0 < AA) {
            s4 = *(const float4*)(sc + a0);
            m = (unsigned)(s4.x >= 0.1f)
              | ((unsigned)(s4.y >= 0.1f) << 1)
              | ((unsigned)(s4.z >= 0.1f) << 2)
              | ((unsigned)(s4.w >= 0.1f) << 3);
        }
        int v = __popc(m);
        int inc = v;
        #pragma unroll
        for (int off = 1; off < 32; off <<= 1) {
            int n = __shfl_up_sync(0xFFFFFFFFu, inc, off);
            if (lane >= off) inc += n;
        }
        int exc = inc - v;
        if (lane == 31) swc[wid] = (unsigned)inc;
        __syncthreads();
        if (a0 < AA && m) {
            int chunk = 4 * it + (wid >> 1);
            unsigned p = scpre[chunk] + (unsigned)exc + ((wid & 1) ? swc[wid - 1] : 0u);
            float ss[4] = {s4.x, s4.y, s4.z, s4.w};
            #pragma unroll
            for (int q = 0; q < 4; q++) {
                if ((m >> q) & 1u) {
                    if (p < SCAP)
                        sk[p] = ((unsigned long long)__float_as_uint(ss[q]) << 32) |
                                (unsigned long long)(0xFFFFFFFFu - (unsigned)(a0 + q));
                    p++;
                }
            }
        }
        __syncthreads();
    }

    // ---- rank scan: slot = candidate lane, seg = key segment ----
    {
        int slot = t & 63, seg = t >> 6;         // seg is warp-uniform
        int npass = ((int)cnt + RB * 64 - 1) / (RB * 64);

        for (int p = 0; p < npass; p++) {
            int c = p * (RB * 64) + bl * 64 + slot;
            bool act = (c < (int)cnt);
            unsigned long long mykey = act ? sk[c] : 0ULL;
            int s0 = (int)(((long long)cnt * seg) >> 2);
            int s1 = (int)(((long long)cnt * (seg + 1)) >> 2);
            int rpart = 0;
            if (act) {
                int mm = s0;
                for (; mm + 4 <= s1; mm += 4) {  // broadcast LDS: all lanes same address
                    rpart += (sk[mm]     > mykey);
                    rpart += (sk[mm + 1] > mykey);
                    rpart += (sk[mm + 2] > mykey);
                    rpart += (sk[mm + 3] > mykey);
                }
                for (; mm < s1; mm++) rpart += (sk[mm] > mykey);
            }
            rp[slot][seg] = (unsigned short)rpart;
            __syncthreads();
            if (seg == 0 && act) {
                int r = (int)rp[slot][0] + rp[slot][1] + rp[slot][2] + rp[slot][3];
                if (r < KK) {
                    int idx = (int)(0xFFFFFFFFu - (unsigned)(mykey & 0xFFFFFFFFu));
                    float score = __uint_as_float((unsigned)(mykey >> 32));
                    float cx = __ldg(&basep[idx]);
                    float cy = __ldg(&basep[AA + idx]);
                    float ww = __ldg(&basep[2 * AA + idx]);
                    float hh = __ldg(&basep[3 * AA + idx]);
                    float hw = ww * 0.5f, hv = hh * 0.5f;
                    float x1 = cx - hw, y1 = cy - hv, x2 = cx + hw, y2 = cy + hv;
                    g_boxes[b][r] = make_float4(x1, y1, x2, y2);
                    // scale = DET_SCALE/IMG_SIZE = [1.5, 1.0546875] (exact fp32)
                    float s1f = x1 * 1.5f + 1.0f;
                    float s2f = y1 * 1.0546875f + 1.0f;
                    float s3f = x2 * 1.5f + 1.0f;
                    float s4f = y2 * 1.0546875f + 1.0f;
                    float* d = out + ((size_t)b * KK + r) * 5;
                    d[0] = (s1f + s3f) * 0.5f;
                    d[1] = (s2f + s4f) * 0.5f;
                    d[2] = s3f - s1f;
                    d[3] = s4f - s2f;
                    d[4] = score;
                    out[(size_t)BB * KK * 5 + (size_t)b * KK + r] = 1.0f;
                }
            }
            __syncthreads();
        }
    }

    // ---- tail fill: this block handles chunks bl, bl+RB, ... (scores L1-hot) ----
    {
        int needed = KK - Nv;
        if (needed > 0) {
            for (int cl = bl; cl < NCH; cl += RB) {
                int invpre = 256 * cl - (int)scpre[cl];   // block-uniform
                if (invpre < needed) {                    // uniform branch
                    int a = cl * 256 + t;
                    float s = __ldg(&sc[a]);
                    bool inv = (s < 0.1f);
                    unsigned bal = __ballot_sync(0xFFFFFFFFu, inv);
                    if (lane == 0) wsum[wid] = (unsigned)__popc(bal);
                    __syncthreads();
                    int wbase = 0;
                    #pragma unroll
                    for (int q = 0; q < 8; q++) if (q < wid) wbase += (int)wsum[q];
                    int r = invpre + wbase + __popc(bal & ((1u << lane) - 1u));
                    if (inv && r < needed) {
                        int slotk = Nv + r;
                        float cx = basep[a], cy = basep[AA + a];
                        float ww = basep[2 * AA + a], hh = basep[3 * AA + a];
                        float hw = ww * 0.5f, hv = hh * 0.5f;
                        float x1 = cx - hw, y1 = cy - hv, x2 = cx + hw, y2 = cy + hv;
                        float s1f = x1 * 1.5f + 1.0f;
                        float s2f = y1 * 1.0546875f + 1.0f;
                        float s3f = x2 * 1.5f + 1.0f;
                        float s4f = y2 * 1.0546875f + 1.0f;
                        float* d = out + ((size_t)b * KK + slotk) * 5;
                        d[0] = (s1f + s3f) * 0.5f;
                        d[1] = (s2f + s4f) * 0.5f;
                        d[2] = s3f - s1f;
                        d[3] = s4f - s2f;
                        d[4] = -1.0f;
                        out[(size_t)BB * KK * 5 + (size_t)b * KK + slotk] = 0.0f;
                    }
                    __syncthreads();   // wsum reuse guard (uniform)
                }
            }
        }
    }

    // PDL: allow K3's grid to launch as early as possible
    cudaTriggerProgrammaticLaunchCompletion();
}

// ======== K3: conflict pairs + last-tile-done greedy resolution ========
__global__ void __launch_bounds__(256) k3_pairs_resolve(float* __restrict__ out) {
    // PDL: wait until K2's writes (g_nv, g_boxes, out) are visible
    cudaGridDependencySynchronize();

    int b = blockIdx.y, bx = blockIdx.x;
    int t = threadIdx.x;

    int Nv = __ldg(&g_nv[b]);
    int nt = (Nv + TILE - 1) / TILE;
    int T = nt * (nt + 1) / 2;
    if (bx >= T) return;

    __shared__ float4 sbi[TILE];
    __shared__ float  sai[TILE];
    __shared__ float4 sbj[TILE];
    __shared__ float  saj[TILE];
    __shared__ int    swin;
    __shared__ unsigned sp[PCAP];        // 2 KB
    __shared__ unsigned char skeep[KK];  // 2 KB

    int i = 0, S = 0;
    while (bx >= S + (nt - i)) { S += nt - i; i++; }
    int j = i + (bx - S);
    int i0 = i * TILE, j0 = j * TILE;

    if (t < TILE) {
        float4 bi = (i0 + t < Nv) ? g_boxes[b][i0 + t] : make_float4(0.f, 0.f, 0.f, 0.f);
        sbi[t] = bi; sai[t] = (bi.z - bi.x) * (bi.w - bi.y);
    } else if (t < 2 * TILE) {
        int u = t - TILE;
        float4 bj = (j0 + u < Nv) ? g_boxes[b][j0 + u] : make_float4(0.f, 0.f, 0.f, 0.f);
        sbj[u] = bj; saj[u] = (bj.z - bj.x) * (bj.w - bj.y);
    }
    __syncthreads();

    int jl = t & 63;
    int jj = j0 + jl;
    if (jj < Nv) {
        float4 bj = sbj[jl];
        float aj = saj[jl];
        #pragma unroll
        for (int q = 0; q < 16; q++) {
            int ii = (t >> 6) + q * 4;
            int gi = i0 + ii;
            if (gi >= Nv || gi >= jj) continue;
            float4 bi = sbi[ii];
            float lx = fmaxf(bi.x, bj.x), ly = fmaxf(bi.y, bj.y);
            float rx = fminf(bi.z, bj.z), ry = fminf(bi.w, bj.w);
            float iw = fmaxf(rx - lx, 0.f), ih = fmaxf(ry - ly, 0.f);
            float inter = iw * ih;
            // iou > 0.7  <=>  inter > 0.7 * union   (union > 0)
            if (inter > 0.7f * (sai[ii] + aj - inter)) {
                unsigned pos = atomicAdd(&g_paircnt[b], 1u);
                if (pos < PCAP)
                    g_pairs[b][pos] = ((unsigned)jj << 16) | (unsigned)gi;
            }
        }
    }
    __syncthreads();

    if (t == 0) {
        __threadfence();                                  // publish this tile's pair writes
        unsigned old = atomicAdd(&g_tiledone[b], 1u);
        swin = (old == (unsigned)(T - 1)) ? 1 : 0;
    }
    __syncthreads();
    if (!swin) return;

    // ---- winner block: exact greedy resolution ----
    __threadfence();
    unsigned n = g_paircnt[b];
    if (n > PCAP) n = PCAP;

    for (int k = t; k < KK; k += 256) skeep[k] = (k < Nv) ? 1 : 0;
    for (unsigned p = t; p < n; p += 256) sp[p] = g_pairs[b][p];
    __syncthreads();

    if (t == 0) {
        // sort ascending by packed (j<<16 | i): process suppression targets j ascending
        for (unsigned x = 1; x < n; x++) {
            unsigned v = sp[x];
            int y = (int)x - 1;
            while (y >= 0 && sp[y] > v) { sp[y + 1] = sp[y]; y--; }
            sp[y + 1] = v;
        }
        for (unsigned x = 0; x < n; x++) {
            unsigned v = sp[x];
            int jd = (int)(v >> 16), is = (int)(v & 0xFFFFu);
            if (skeep[is] && skeep[jd]) {
                skeep[jd] = 0;
                out[(size_t)BB * KK * 5 + (size_t)b * KK + jd] = 0.0f;
            }
        }
        g_paircnt[b]  = 0u;   // restore zero-state for next launch
        g_tiledone[b] = 0u;
    }
}

// ---------------- launch ----------------
extern "C" void kernel_launch(void* const* d_in, const int* in_sizes, int n_in,
                              void* d_out, int out_size) {
    const float* preds = (const float*)d_in[0];
    float* out = (float*)d_out;
    (void)in_sizes; (void)n_in; (void)out_size;

    k_main<<<dim3(RB, BB), 256>>>(preds, out);

    cudaLaunchConfig_t cfg = {};
    cfg.gridDim = dim3(528, BB);     // 528 = max tiles (Nv<=2048)
    cfg.blockDim = dim3(256, 1, 1);
    cfg.dynamicSmemBytes = 0;
    cfg.stream = 0;
    cudaLaunchAttribute attr[1];
    attr[0].id = cudaLaunchAttributeProgrammaticStreamSerialization;
    attr[0].val.programmaticStreamSerializationAllowed = 1;
    cfg.attrs = attr;
    cfg.numAttrs = 1;
    cudaLaunchKernelEx(&cfg, k3_pairs_resolve, out);
}

// round 12
// speedup vs baseline: 1.1148x; 1.1148x over previous
#include <cuda_runtime.h>
#include <cuda_bf16.h>
#include <stdint.h>

#define BB 8
#define AA 26880
#define KK 2048
#define NCH 105          // 26880/256 chunks per batch
#define SCAP 4096        // staged-key capacity (Nv ~ 1344)
#define PCAP 512         // conflict-pair capacity per batch (expected ~10)
#define RB 32            // rank/tail blocks per batch in K2
#define K1B 27           // compaction blocks per batch in K1
#define K3B 528          // tile blocks per batch in K3 (max tiles for Nv<=2048)
#define TILE 64
#define SPIN_MAX 4194304u   // deadlock diagnostic bound (~170ms); never hit legitimately

// ---------------- device scratch (counters 0 at entry, reset by K3 winner) ----------------
__device__ unsigned            g_cvcnt[BB * NCH];          // per-chunk valid count
__device__ unsigned long long  g_ckeys[BB * NCH * 256];    // chunk-local compacted keys
__device__ int                 g_nv[BB];
__device__ float4              g_boxes[BB][KK];
__device__ unsigned            g_paircnt[BB];
__device__ unsigned            g_pairs[BB][PCAP];
__device__ unsigned            g_adone[BB];                // K1 blocks done per batch
__device__ unsigned            g_bdone[BB];                // K2 blocks done per batch
__device__ unsigned            g_tiledone[BB];             // K3 block arrivals per batch

// release: every thread fences its own stores, then one arrival per block
__device__ __forceinline__ void ctr_release(unsigned* ctr) {
    __threadfence();
    __syncthreads();
    if (threadIdx.x == 0) atomicAdd(ctr, 1u);
}
// acquire: wait for `target` arrivals, then fence + block-sync (bounded: diagnostic)
__device__ __forceinline__ void ctr_acquire(unsigned* ctr, unsigned target) {
    if (threadIdx.x == 0) {
        unsigned spins = 0;
        while (*(volatile unsigned*)ctr < target && ++spins < SPIN_MAX) __nanosleep(32);
        __threadfence();
    }
    __syncthreads();
}

// ======== K1: vectorized chunked compaction (float4, warp-scan, no atomics) ========
// key = (score_bits << 32) | (0xFFFFFFFF - idx): descending key order gives
// score desc, idx asc on ties (positive floats are bit-order-preserving).
__global__ void __launch_bounds__(256) k1_compact(const float* __restrict__ preds) {
    cudaTriggerProgrammaticLaunchCompletion();   // let K2's grid become resident NOW

    int b = blockIdx.y;
    int t = threadIdx.x, wid = t >> 5, lane = t & 31;
    __shared__ unsigned swc[8];    // per-warp valid totals

    int a0 = blockIdx.x * 1024 + t * 4;          // 4 consecutive anchors per thread
    bool inb = (a0 < AA);                        // AA % 4 == 0, float4-aligned
    float4 s4 = make_float4(0.f, 0.f, 0.f, 0.f);
    if (inb) s4 = *(const float4*)(preds + (size_t)b * 5 * AA + (size_t)4 * AA + a0);

    unsigned m = 0;
    if (inb) {
        m = (unsigned)(s4.x >= 0.1f)
          | ((unsigned)(s4.y >= 0.1f) << 1)
          | ((unsigned)(s4.z >= 0.1f) << 2)
          | ((unsigned)(s4.w >= 0.1f) << 3);
    }
    int v = __popc(m);
    int inc = v;
    #pragma unroll
    for (int off = 1; off < 32; off <<= 1) {
        int n = __shfl_up_sync(0xFFFFFFFFu, inc, off);
        if (lane >= off) inc += n;
    }
    int exc = inc - v;
    if (lane == 31) swc[wid] = (unsigned)inc;
    __syncthreads();

    int cib = wid >> 1;                    // chunk within block (0..3), chunk = 2 warps
    int cl = blockIdx.x * 4 + cib;
    if (cl < NCH && inb) {
        unsigned p = (unsigned)exc + ((wid & 1) ? swc[wid - 1] : 0u);
        unsigned long long* dst = &g_ckeys[((size_t)b * NCH + cl) * 256];
        float ss[4] = {s4.x, s4.y, s4.z, s4.w};
        #pragma unroll
        for (int q = 0; q < 4; q++) {
            if ((m >> q) & 1u) {
                dst[p++] =
                    ((unsigned long long)__float_as_uint(ss[q]) << 32) |
                    (unsigned long long)(0xFFFFFFFFu - (unsigned)(a0 + q));
            }
        }
    }
    if (cl < NCH && (t & 63) == 0)
        g_cvcnt[b * NCH + cl] = swc[cib * 2] + swc[cib * 2 + 1];

    ctr_release(&g_adone[b]);              // signal this batch's compaction progress
}

// ======== K2: rank sort (thread-per-candidate, 4-way split scan) + tail fill ========
__global__ void __launch_bounds__(256) k2_rank_tail(const float* __restrict__ preds,
                                                    float* __restrict__ out) {
    cudaTriggerProgrammaticLaunchCompletion();   // let K3's grid become resident NOW

    int b = blockIdx.y, bl = blockIdx.x;       // bl in [0, RB)
    int t = threadIdx.x, wid = t >> 5, lane = t & 31;

    __shared__ unsigned long long sk[SCAP];    // 32 KB
    __shared__ unsigned scv[NCH];
    __shared__ unsigned scpre[NCH + 1];
    __shared__ unsigned short rp[64][4];
    __shared__ unsigned wsum[8];
    __shared__ unsigned s_cnt;

    ctr_acquire(&g_adone[b], K1B);             // wait only for THIS batch's compaction

    if (t < NCH) scv[t] = g_cvcnt[b * NCH + t];
    __syncthreads();
    if (t == 0) {
        unsigned run = 0;
        for (int x = 0; x < NCH; x++) { scpre[x] = run; run += scv[x]; }
        scpre[NCH] = run;
        s_cnt = (run > SCAP) ? SCAP : run;
    }
    __syncthreads();
    unsigned cnt = s_cnt;
    int Nv = ((int)cnt < KK) ? (int)cnt : KK;
    if (bl == 0 && t == 0) g_nv[b] = Nv;

    // stage keys contiguously (warp per chunk)
    for (int cl = wid; cl < NCH; cl += 8) {
        unsigned base = scpre[cl], n = scv[cl];
        const unsigned long long* src = &g_ckeys[((size_t)b * NCH + cl) * 256];
        for (unsigned j = lane; j < n; j += 32) {
            unsigned d = base + j;
            if (d < SCAP) sk[d] = __ldg(&src[j]);
        }
    }
    __syncthreads();

    // rank scan: slot = candidate lane, seg = key segment
    int slot = t & 63, seg = t >> 6;           // seg is warp-uniform
    int npass = ((int)cnt + RB * 64 - 1) / (RB * 64);
    const float* basep = preds + (size_t)b * 5 * AA;

    for (int p = 0; p < npass; p++) {
        int c = p * (RB * 64) + bl * 64 + slot;
        bool act = (c < (int)cnt);
        unsigned long long mykey = act ? sk[c] : 0ULL;
        int s0 = (int)(((long long)cnt * seg) >> 2);
        int s1 = (int)(((long long)cnt * (seg + 1)) >> 2);
        int rpart = 0;
        if (act) {
            int mm = s0;
            for (; mm + 4 <= s1; mm += 4) {    // broadcast LDS: all lanes same address
                rpart += (sk[mm]     > mykey);
                rpart += (sk[mm + 1] > mykey);
                rpart += (sk[mm + 2] > mykey);
                rpart += (sk[mm + 3] > mykey);
            }
            for (; mm < s1; mm++) rpart += (sk[mm] > mykey);
        }
        rp[slot][seg] = (unsigned short)rpart;
        __syncthreads();
        if (seg == 0 && act) {
            int r = (int)rp[slot][0] + rp[slot][1] + rp[slot][2] + rp[slot][3];
            if (r < KK) {
                int idx = (int)(0xFFFFFFFFu - (unsigned)(mykey & 0xFFFFFFFFu));
                float score = __uint_as_float((unsigned)(mykey >> 32));
                float cx = __ldg(&basep[idx]);
                float cy = __ldg(&basep[AA + idx]);
                float ww = __ldg(&basep[2 * AA + idx]);
                float hh = __ldg(&basep[3 * AA + idx]);
                float hw = ww * 0.5f, hv = hh * 0.5f;
                float x1 = cx - hw, y1 = cy - hv, x2 = cx + hw, y2 = cy + hv;
                g_boxes[b][r] = make_float4(x1, y1, x2, y2);
                // scale = DET_SCALE/IMG_SIZE = [1.5, 1.0546875] (exact fp32)
                float s1f = x1 * 1.5f + 1.0f;
                float s2f = y1 * 1.0546875f + 1.0f;
                float s3f = x2 * 1.5f + 1.0f;
                float s4f = y2 * 1.0546875f + 1.0f;
                float* d = out + ((size_t)b * KK + r) * 5;
                d[0] = (s1f + s3f) * 0.5f;
                d[1] = (s2f + s4f) * 0.5f;
                d[2] = s3f - s1f;
                d[3] = s4f - s2f;
                d[4] = score;
                out[(size_t)BB * KK * 5 + (size_t)b * KK + r] = 1.0f;
            }
        }
        __syncthreads();
    }

    // tail fill: this block handles chunks bl, bl+RB, ...
    int needed = KK - Nv;
    if (needed > 0) {
        const float* sc = basep + (size_t)4 * AA;
        for (int cl = bl; cl < NCH; cl += RB) {
            int invpre = 256 * cl - (int)scpre[cl];   // block-uniform
            if (invpre < needed) {                    // uniform branch
                int a = cl * 256 + t;
                float s = __ldg(&sc[a]);
                bool inv = (s < 0.1f);
                unsigned bal = __ballot_sync(0xFFFFFFFFu, inv);
                if (lane == 0) wsum[wid] = (unsigned)__popc(bal);
                __syncthreads();
                int wbase = 0;
                #pragma unroll
                for (int q = 0; q < 8; q++) if (q < wid) wbase += (int)wsum[q];
                int r = invpre + wbase + __popc(bal & ((1u << lane) - 1u));
                if (inv && r < needed) {
                    int slotk = Nv + r;
                    float cx = basep[a], cy = basep[AA + a];
                    float ww = basep[2 * AA + a], hh = basep[3 * AA + a];
                    float hw = ww * 0.5f, hv = hh * 0.5f;
                    float x1 = cx - hw, y1 = cy - hv, x2 = cx + hw, y2 = cy + hv;
                    float s1f = x1 * 1.5f + 1.0f;
                    float s2f = y1 * 1.0546875f + 1.0f;
                    float s3f = x2 * 1.5f + 1.0f;
                    float s4f = y2 * 1.0546875f + 1.0f;
                    float* d = out + ((size_t)b * KK + slotk) * 5;
                    d[0] = (s1f + s3f) * 0.5f;
                    d[1] = (s2f + s4f) * 0.5f;
                    d[2] = s3f - s1f;
                    d[3] = s4f - s2f;
                    d[4] = -1.0f;
                    out[(size_t)BB * KK * 5 + (size_t)b * KK + slotk] = 0.0f;
                }
                __syncthreads();   // wsum reuse guard (uniform)
            }
        }
    }

    ctr_release(&g_bdone[b]);    // boxes + dets for this batch published
}

// ======== K3: conflict pairs + all-arrive greedy resolution + counter reset ========
__global__ void __launch_bounds__(256) k3_pairs_resolve(float* __restrict__ out) {
    int b = blockIdx.y, bx = blockIdx.x;
    int t = threadIdx.x;

    __shared__ float4 sbi[TILE];
    __shared__ float  sai[TILE];
    __shared__ float4 sbj[TILE];
    __shared__ float  saj[TILE];
    __shared__ int    swin;
    __shared__ unsigned sp[PCAP];        // 2 KB
    __shared__ unsigned char skeep[KK];  // 2 KB

    ctr_acquire(&g_bdone[b], RB);        // wait only for THIS batch's boxes

    int Nv = g_nv[b];
    int nt = (Nv + TILE - 1) / TILE;
    int T = nt * (nt + 1) / 2;

    if (bx < T) {
        int i = 0, S = 0;
        while (bx >= S + (nt - i)) { S += nt - i; i++; }
        int j = i + (bx - S);
        int i0 = i * TILE, j0 = j * TILE;

        if (t < TILE) {
            float4 bi = (i0 + t < Nv) ? g_boxes[b][i0 + t] : make_float4(0.f, 0.f, 0.f, 0.f);
            sbi[t] = bi; sai[t] = (bi.z - bi.x) * (bi.w - bi.y);
        } else if (t < 2 * TILE) {
            int u = t - TILE;
            float4 bj = (j0 + u < Nv) ? g_boxes[b][j0 + u] : make_float4(0.f, 0.f, 0.f, 0.f);
            sbj[u] = bj; saj[u] = (bj.z - bj.x) * (bj.w - bj.y);
        }
        __syncthreads();

        int jl = t & 63;
        int jj = j0 + jl;
        if (jj < Nv) {
            float4 bj = sbj[jl];
            float aj = saj[jl];
            #pragma unroll
            for (int q = 0; q < 16; q++) {
                int ii = (t >> 6) + q * 4;
                int gi = i0 + ii;
                if (gi >= Nv || gi >= jj) continue;
                float4 bi = sbi[ii];
                float lx = fmaxf(bi.x, bj.x), ly = fmaxf(bi.y, bj.y);
                float rx = fminf(bi.z, bj.z), ry = fminf(bi.w, bj.w);
                float iw = fmaxf(rx - lx, 0.f), ih = fmaxf(ry - ly, 0.f);
                float inter = iw * ih;
                // iou > 0.7  <=>  inter > 0.7 * union   (union > 0)
                if (inter > 0.7f * (sai[ii] + aj - inter)) {
                    unsigned pos = atomicAdd(&g_paircnt[b], 1u);
                    if (pos < PCAP)
                        g_pairs[b][pos] = ((unsigned)jj << 16) | (unsigned)gi;
                }
            }
        }
        __syncthreads();
    }

    // ALL K3B blocks of this batch arrive (dead tiles too) -> winner is elected only
    // after every batch-b block has passed its spin and finished its tile work.
    if (t == 0) {
        __threadfence();
        unsigned old = atomicAdd(&g_tiledone[b], 1u);
        swin = (old == (unsigned)(K3B - 1)) ? 1 : 0;
    }
    __syncthreads();
    if (!swin) return;

    // ---- winner block: exact greedy resolution + restore zero-state ----
    __threadfence();
    unsigned n = g_paircnt[b];
    if (n > PCAP) n = PCAP;

    for (int k = t; k < KK; k += 256) skeep[k] = (k < Nv) ? 1 : 0;
    for (unsigned p = t; p < n; p += 256) sp[p] = g_pairs[b][p];
    __syncthreads();

    if (t == 0) {
        // sort ascending by packed (j<<16 | i): process suppression targets j ascending
        for (unsigned x = 1; x < n; x++) {
            unsigned v = sp[x];
            int y = (int)x - 1;
            while (y >= 0 && sp[y] > v) { sp[y + 1] = sp[y]; y--; }
            sp[y + 1] = v;
        }
        for (unsigned x = 0; x < n; x++) {
            unsigned v = sp[x];
            int jd = (int)(v >> 16), is = (int)(v & 0xFFFFu);
            if (skeep[is] && skeep[jd]) {
                skeep[jd] = 0;
                out[(size_t)BB * KK * 5 + (size_t)b * KK + jd] = 0.0f;
            }
        }
        // all readers of these counters (batch b) are provably past their spins
        g_paircnt[b]  = 0u;
        g_adone[b]    = 0u;
        g_bdone[b]    = 0u;
        g_tiledone[b] = 0u;
    }
}

// ---------------- launch (PDL-overlapped, counter-synchronized) ----------------
static void launch_pdl2(void (*kern)(const float*, float*),
                        dim3 grid, const float* preds, float* out) {
    cudaLaunchConfig_t cfg = {};
    cfg.gridDim = grid; cfg.blockDim = dim3(256, 1, 1);
    cfg.dynamicSmemBytes = 0; cfg.stream = 0;
    cudaLaunchAttribute attr[1];
    attr[0].id = cudaLaunchAttributeProgrammaticStreamSerialization;
    attr[0].val.programmaticStreamSerializationAllowed = 1;
    cfg.attrs = attr; cfg.numAttrs = 1;
    cudaLaunchKernelEx(&cfg, kern, preds, out);
}
static void launch_pdl1(void (*kern)(float*), dim3 grid, float* out) {
    cudaLaunchConfig_t cfg = {};
    cfg.gridDim = grid; cfg.blockDim = dim3(256, 1, 1);
    cfg.dynamicSmemBytes = 0; cfg.stream = 0;
    cudaLaunchAttribute attr[1];
    attr[0].id = cudaLaunchAttributeProgrammaticStreamSerialization;
    attr[0].val.programmaticStreamSerializationAllowed = 1;
    cfg.attrs = attr; cfg.numAttrs = 1;
    cudaLaunchKernelEx(&cfg, kern, out);
}

extern "C" void kernel_launch(void* const* d_in, const int* in_sizes, int n_in,
                              void* d_out, int out_size) {
    const float* preds = (const float*)d_in[0];
    float* out = (float*)d_out;
    (void)in_sizes; (void)n_in; (void)out_size;

    k1_compact<<<dim3(K1B, BB), 256>>>(preds);
    launch_pdl2(k2_rank_tail, dim3(RB, BB), preds, out);
    launch_pdl1(k3_pairs_resolve, dim3(K3B, BB), out);
}

// round 13
// speedup vs baseline: 1.3620x; 1.2217x over previous
#include <cuda_runtime.h>
#include <cuda_bf16.h>
#include <stdint.h>

#define BB 8
#define AA 26880
#define KK 2048
#define NCH 105          // 26880/256 chunks per batch
#define SCAP 4096        // staged-key capacity (Nv ~ 1344)
#define PCAP 512         // conflict-pair capacity per batch (expected ~10)
#define K1B 27           // compaction-role blocks per batch
#define RB 32            // rank/tail-role blocks per batch
#define KAB (K1B + RB)   // 59 blocks per batch in KA
#define K3B 528          // tile blocks per batch in K3 (max tiles for Nv<=2048)
#define TILE 64
#define SPIN_MAX 4194304u   // diagnostic bound; never hit legitimately

// ---------------- device scratch (counters 0 at entry, reset by K3 winner) ----------------
__device__ unsigned            g_cvcnt[BB * NCH];          // per-chunk valid count
__device__ unsigned long long  g_ckeys[BB * NCH * 256];    // chunk-local compacted keys
__device__ int                 g_nv[BB];
__device__ float4              g_boxes[BB][KK];
__device__ unsigned            g_paircnt[BB];
__device__ unsigned            g_pairs[BB][PCAP];
__device__ unsigned            g_adone[BB];                // compaction-role blocks done
__device__ unsigned            g_tiledone[BB];             // K3 block arrivals

// ======== KA: compaction role (bl<27) || rank+tail role (bl>=27), one launch ========
// key = (score_bits << 32) | (0xFFFFFFFF - idx): descending key order gives
// score desc, idx asc on ties (positive floats are bit-order-preserving).
__global__ void __launch_bounds__(256) kA_main(const float* __restrict__ preds,
                                               float* __restrict__ out) {
    const int b = blockIdx.y;
    const int t = threadIdx.x, wid = t >> 5, lane = t & 31;

    __shared__ unsigned long long sk[SCAP];    // 32 KB (consumer role)
    __shared__ unsigned scv[NCH];
    __shared__ unsigned scpre[NCH + 1];
    __shared__ unsigned short rp[64][4];
    __shared__ unsigned wsum[8];               // also used as swc by producer role
    __shared__ unsigned s_cnt;

    if (blockIdx.x < K1B) {
        // ---------------- producer role: vectorized chunked compaction ----------------
        int a0 = blockIdx.x * 1024 + t * 4;          // 4 consecutive anchors per thread
        bool inb = (a0 < AA);                        // AA % 4 == 0, float4-aligned
        float4 s4 = make_float4(0.f, 0.f, 0.f, 0.f);
        if (inb) s4 = *(const float4*)(preds + (size_t)b * 5 * AA + (size_t)4 * AA + a0);

        unsigned m = 0;
        if (inb) {
            m = (unsigned)(s4.x >= 0.1f)
              | ((unsigned)(s4.y >= 0.1f) << 1)
              | ((unsigned)(s4.z >= 0.1f) << 2)
              | ((unsigned)(s4.w >= 0.1f) << 3);
        }
        int v = __popc(m);
        int inc = v;
        #pragma unroll
        for (int off = 1; off < 32; off <<= 1) {
            int n = __shfl_up_sync(0xFFFFFFFFu, inc, off);
            if (lane >= off) inc += n;
        }
        int exc = inc - v;
        if (lane == 31) wsum[wid] = (unsigned)inc;
        __syncthreads();

        int cib = wid >> 1;                    // chunk within block (0..3), chunk = 2 warps
        int cl = blockIdx.x * 4 + cib;
        if (cl < NCH && inb) {
            unsigned p = (unsigned)exc + ((wid & 1) ? wsum[wid - 1] : 0u);
            unsigned long long* dst = &g_ckeys[((size_t)b * NCH + cl) * 256];
            float ss[4] = {s4.x, s4.y, s4.z, s4.w};
            #pragma unroll
            for (int q = 0; q < 4; q++) {
                if ((m >> q) & 1u) {
                    dst[p++] =
                        ((unsigned long long)__float_as_uint(ss[q]) << 32) |
                        (unsigned long long)(0xFFFFFFFFu - (unsigned)(a0 + q));
                }
            }
        }
        if (cl < NCH && (t & 63) == 0)
            g_cvcnt[b * NCH + cl] = wsum[cib * 2] + wsum[cib * 2 + 1];

        // release: publish this block's keys + counts
        __threadfence();
        __syncthreads();
        if (t == 0) atomicAdd(&g_adone[b], 1u);
        return;
    }

    // ---------------- consumer role: rank sort + tail fill ----------------
    const int bl = blockIdx.x - K1B;               // [0, RB)

    // acquire: wait for THIS batch's 27 producer blocks
    if (t == 0) {
        unsigned spins = 0;
        while (*(volatile unsigned*)&g_adone[b] < (unsigned)K1B && ++spins < SPIN_MAX)
            __nanosleep(32);
        __threadfence();
    }
    __syncthreads();

    if (t < NCH) scv[t] = g_cvcnt[b * NCH + t];
    __syncthreads();
    if (t == 0) {
        unsigned run = 0;
        for (int x = 0; x < NCH; x++) { scpre[x] = run; run += scv[x]; }
        scpre[NCH] = run;
        s_cnt = (run > SCAP) ? SCAP : run;
    }
    __syncthreads();
    unsigned cnt = s_cnt;
    int Nv = ((int)cnt < KK) ? (int)cnt : KK;
    if (bl == 0 && t == 0) g_nv[b] = Nv;

    // stage keys contiguously (warp per chunk)
    for (int cl = wid; cl < NCH; cl += 8) {
        unsigned base = scpre[cl], n = scv[cl];
        const unsigned long long* src = &g_ckeys[((size_t)b * NCH + cl) * 256];
        for (unsigned j = lane; j < n; j += 32) {
            unsigned d = base + j;
            if (d < SCAP) sk[d] = __ldg(&src[j]);
        }
    }
    __syncthreads();

    // rank scan: slot = candidate lane, seg = key segment
    int slot = t & 63, seg = t >> 6;               // seg is warp-uniform
    int npass = ((int)cnt + RB * 64 - 1) / (RB * 64);
    const float* basep = preds + (size_t)b * 5 * AA;

    for (int p = 0; p < npass; p++) {
        int c = p * (RB * 64) + bl * 64 + slot;
        bool act = (c < (int)cnt);
        unsigned long long mykey = act ? sk[c] : 0ULL;
        int s0 = (int)(((long long)cnt * seg) >> 2);
        int s1 = (int)(((long long)cnt * (seg + 1)) >> 2);
        int rpart = 0;
        if (act) {
            int mm = s0;
            for (; mm + 4 <= s1; mm += 4) {        // broadcast LDS: all lanes same address
                rpart += (sk[mm]     > mykey);
                rpart += (sk[mm + 1] > mykey);
                rpart += (sk[mm + 2] > mykey);
                rpart += (sk[mm + 3] > mykey);
            }
            for (; mm < s1; mm++) rpart += (sk[mm] > mykey);
        }
        rp[slot][seg] = (unsigned short)rpart;
        __syncthreads();
        if (seg == 0 && act) {
            int r = (int)rp[slot][0] + rp[slot][1] + rp[slot][2] + rp[slot][3];
            if (r < KK) {
                int idx = (int)(0xFFFFFFFFu - (unsigned)(mykey & 0xFFFFFFFFu));
                float score = __uint_as_float((unsigned)(mykey >> 32));
                float cx = __ldg(&basep[idx]);
                float cy = __ldg(&basep[AA + idx]);
                float ww = __ldg(&basep[2 * AA + idx]);
                float hh = __ldg(&basep[3 * AA + idx]);
                float hw = ww * 0.5f, hv = hh * 0.5f;
                float x1 = cx - hw, y1 = cy - hv, x2 = cx + hw, y2 = cy + hv;
                g_boxes[b][r] = make_float4(x1, y1, x2, y2);
                // scale = DET_SCALE/IMG_SIZE = [1.5, 1.0546875] (exact fp32)
                float s1f = x1 * 1.5f + 1.0f;
                float s2f = y1 * 1.0546875f + 1.0f;
                float s3f = x2 * 1.5f + 1.0f;
                float s4f = y2 * 1.0546875f + 1.0f;
                float* d = out + ((size_t)b * KK + r) * 5;
                d[0] = (s1f + s3f) * 0.5f;
                d[1] = (s2f + s4f) * 0.5f;
                d[2] = s3f - s1f;
                d[3] = s4f - s2f;
                d[4] = score;
                out[(size_t)BB * KK * 5 + (size_t)b * KK + r] = 1.0f;
            }
        }
        __syncthreads();
    }

    // tail fill: this block handles chunks bl, bl+RB, ...
    int needed = KK - Nv;
    if (needed > 0) {
        const float* sc = basep + (size_t)4 * AA;
        for (int cl = bl; cl < NCH; cl += RB) {
            int invpre = 256 * cl - (int)scpre[cl];   // block-uniform
            if (invpre < needed) {                    // uniform branch
                int a = cl * 256 + t;
                float s = __ldg(&sc[a]);
                bool inv = (s < 0.1f);
                unsigned bal = __ballot_sync(0xFFFFFFFFu, inv);
                if (lane == 0) wsum[wid] = (unsigned)__popc(bal);
                __syncthreads();
                int wbase = 0;
                #pragma unroll
                for (int q = 0; q < 8; q++) if (q < wid) wbase += (int)wsum[q];
                int r = invpre + wbase + __popc(bal & ((1u << lane) - 1u));
                if (inv && r < needed) {
                    int slotk = Nv + r;
                    float cx = basep[a], cy = basep[AA + a];
                    float ww = basep[2 * AA + a], hh = basep[3 * AA + a];
                    float hw = ww * 0.5f, hv = hh * 0.5f;
                    float x1 = cx - hw, y1 = cy - hv, x2 = cx + hw, y2 = cy + hv;
                    float s1f = x1 * 1.5f + 1.0f;
                    float s2f = y1 * 1.0546875f + 1.0f;
                    float s3f = x2 * 1.5f + 1.0f;
                    float s4f = y2 * 1.0546875f + 1.0f;
                    float* d = out + ((size_t)b * KK + slotk) * 5;
                    d[0] = (s1f + s3f) * 0.5f;
                    d[1] = (s2f + s4f) * 0.5f;
                    d[2] = s3f - s1f;
                    d[3] = s4f - s2f;
                    d[4] = -1.0f;
                    out[(size_t)BB * KK * 5 + (size_t)b * KK + slotk] = 0.0f;
                }
                __syncthreads();   // wsum reuse guard (uniform)
            }
        }
    }

    // PDL: allow K3's grid to launch as early as possible
    cudaTriggerProgrammaticLaunchCompletion();
}

// ======== K3: conflict pairs + last-tile-done greedy resolution (round-8 proven) ========
__global__ void __launch_bounds__(256) k3_pairs_resolve(float* __restrict__ out) {
    // PDL: wait until the whole KA grid has completed (g_nv, g_boxes, out visible)
    cudaGridDependencySynchronize();

    int b = blockIdx.y, bx = blockIdx.x;
    int t = threadIdx.x;

    int Nv = __ldg(&g_nv[b]);
    int nt = (Nv + TILE - 1) / TILE;
    int T = nt * (nt + 1) / 2;
    if (bx >= T) return;

    __shared__ float4 sbi[TILE];
    __shared__ float  sai[TILE];
    __shared__ float4 sbj[TILE];
    __shared__ float  saj[TILE];
    __shared__ int    swin;
    __shared__ unsigned sp[PCAP];        // 2 KB
    __shared__ unsigned char skeep[KK];  // 2 KB

    int i = 0, S = 0;
    while (bx >= S + (nt - i)) { S += nt - i; i++; }
    int j = i + (bx - S);
    int i0 = i * TILE, j0 = j * TILE;

    if (t < TILE) {
        float4 bi = (i0 + t < Nv) ? g_boxes[b][i0 + t] : make_float4(0.f, 0.f, 0.f, 0.f);
        sbi[t] = bi; sai[t] = (bi.z - bi.x) * (bi.w - bi.y);
    } else if (t < 2 * TILE) {
        int u = t - TILE;
        float4 bj = (j0 + u < Nv) ? g_boxes[b][j0 + u] : make_float4(0.f, 0.f, 0.f, 0.f);
        sbj[u] = bj; saj[u] = (bj.z - bj.x) * (bj.w - bj.y);
    }
    __syncthreads();

    int jl = t & 63;
    int jj = j0 + jl;
    if (jj < Nv) {
        float4 bj = sbj[jl];
        float aj = saj[jl];
        #pragma unroll
        for (int q = 0; q < 16; q++) {
            int ii = (t >> 6) + q * 4;
            int gi = i0 + ii;
            if (gi >= Nv || gi >= jj) continue;
            float4 bi = sbi[ii];
            float lx = fmaxf(bi.x, bj.x), ly = fmaxf(bi.y, bj.y);
            float rx = fminf(bi.z, bj.z), ry = fminf(bi.w, bj.w);
            float iw = fmaxf(rx - lx, 0.f), ih = fmaxf(ry - ly, 0.f);
            float inter = iw * ih;
            // iou > 0.7  <=>  inter > 0.7 * union   (union > 0)
            if (inter > 0.7f * (sai[ii] + aj - inter)) {
                unsigned pos = atomicAdd(&g_paircnt[b], 1u);
                if (pos < PCAP)
                    g_pairs[b][pos] = ((unsigned)jj << 16) | (unsigned)gi;
            }
        }
    }
    __syncthreads();

    if (t == 0) {
        __threadfence();                                  // publish this tile's pair writes
        unsigned old = atomicAdd(&g_tiledone[b], 1u);
        swin = (old == (unsigned)(T - 1)) ? 1 : 0;
    }
    __syncthreads();
    if (!swin) return;

    // ---- winner block: exact greedy resolution + restore zero-state ----
    __threadfence();
    unsigned n = g_paircnt[b];
    if (n > PCAP) n = PCAP;

    for (int k = t; k < KK; k += 256) skeep[k] = (k < Nv) ? 1 : 0;
    for (unsigned p = t; p < n; p += 256) sp[p] = g_pairs[b][p];
    __syncthreads();

    if (t == 0) {
        // sort ascending by packed (j<<16 | i): process suppression targets j ascending
        for (unsigned x = 1; x < n; x++) {
            unsigned v = sp[x];
            int y = (int)x - 1;
            while (y >= 0 && sp[y] > v) { sp[y + 1] = sp[y]; y--; }
            sp[y + 1] = v;
        }
        for (unsigned x = 0; x < n; x++) {
            unsigned v = sp[x];
            int jd = (int)(v >> 16), is = (int)(v & 0xFFFFu);
            if (skeep[is] && skeep[jd]) {
                skeep[jd] = 0;
                out[(size_t)BB * KK * 5 + (size_t)b * KK + jd] = 0.0f;
            }
        }
        // restore zero-state for next launch (all KA blocks completed before K3 began)
        g_paircnt[b]  = 0u;
        g_adone[b]    = 0u;
        g_tiledone[b] = 0u;
    }
}

// ---------------- launch ----------------
extern "C" void kernel_launch(void* const* d_in, const int* in_sizes, int n_in,
                              void* d_out, int out_size) {
    const float* preds = (const float*)d_in[0];
    float* out = (float*)d_out;
    (void)in_sizes; (void)n_in; (void)out_size;

    kA_main<<<dim3(KAB, BB), 256>>>(preds, out);

    cudaLaunchConfig_t cfg = {};
    cfg.gridDim = dim3(K3B, BB);
    cfg.blockDim = dim3(256, 1, 1);
    cfg.dynamicSmemBytes = 0;
    cfg.stream = 0;
    cudaLaunchAttribute attr[1];
    attr[0].id = cudaLaunchAttributeProgrammaticStreamSerialization;
    attr[0].val.programmaticStreamSerializationAllowed = 1;
    cfg.attrs = attr;
    cfg.numAttrs = 1;
    cudaLaunchKernelEx(&cfg, k3_pairs_resolve, out);
}